// round 1
// baseline (speedup 1.0000x reference)
#include <cuda_runtime.h>
#include <stdint.h>

// Problem constants (from reference): FEAT=192 per corner, V=98304, 3F=589824.
// Every vertex has degree exactly 6 (flat = perm(arange(3F) % V), 3F = 6*V),
// but we compute counts dynamically and guard with STRIDE=8 slack.
#define FEAT    192
#define FEAT4   48          // FEAT / 4 (float4 columns)
#define V_MAX   98304
#define STRIDE  8           // padded slots per vertex in the inverse map

__device__ int g_counts[V_MAX];
__device__ int g_inv[V_MAX * STRIDE];
__device__ int g_is64;

// ---------------------------------------------------------------------------
// Kernel 1: zero per-vertex counters + detect faces dtype (int32 vs int64).
// For int64 little-endian non-negative indices < 2^31, every odd 32-bit word
// is zero. 32 consecutive zero odd-words from random int32 indices is
// probability ~(1/V)^32 ~ 0, so the ballot test is safe and deterministic.
// ---------------------------------------------------------------------------
__global__ void zero_detect_kernel(const unsigned int* __restrict__ faces_raw, int V)
{
    int t = blockIdx.x * blockDim.x + threadIdx.x;
    if (t < V) g_counts[t] = 0;
    if (blockIdx.x == 0 && threadIdx.x < 32) {
        unsigned int w = faces_raw[2 * threadIdx.x + 1];   // odd words
        unsigned int mask = __ballot_sync(0xffffffffu, w == 0u);
        if (threadIdx.x == 0) g_is64 = (mask == 0xffffffffu) ? 1 : 0;
    }
}

// ---------------------------------------------------------------------------
// Kernel 2: build inverse map vertex -> corner ids via int atomics.
// slot = atomicAdd(counts[v]); inv[v*8 + slot] = corner. Cheap: 2.3MB idx read,
// 589824 spread-address int atomics, 2.3MB scatter write.
// ---------------------------------------------------------------------------
__global__ void build_inv_kernel(const void* __restrict__ faces, int n_corners, int V)
{
    int c = blockIdx.x * blockDim.x + threadIdx.x;
    if (c >= n_corners) return;
    int is64 = g_is64;
    int v;
    if (is64) {
        v = (int)__ldg(((const long long*)faces) + c);
    } else {
        v = __ldg(((const int*)faces) + c);
    }
    if ((unsigned)v >= (unsigned)V) return;  // defensive; never taken on valid input
    int slot = atomicAdd(&g_counts[v], 1);
    if (slot < STRIDE) g_inv[v * STRIDE + slot] = c;
}

// ---------------------------------------------------------------------------
// Kernel 3: gather + mean. One thread per (vertex, float4-column).
// 48 threads cooperate on one vertex; each reads up to STRIDE corner rows'
// float4 at its column (LDG.128, coalesced 768B row chunks), sums, scales by
// 1/count, writes once (STG.128). Fast path fully unrolled for count==6
// (always true here) -> 6 independent in-flight LDG.128 per thread (good MLP).
// ---------------------------------------------------------------------------
__global__ void gather_mean_kernel(const float4* __restrict__ ff,
                                   float4* __restrict__ out, int V)
{
    int t = blockIdx.x * blockDim.x + threadIdx.x;
    int total = V * FEAT4;
    if (t >= total) return;
    int v   = t / FEAT4;       // compile-time const divisor -> mul/shift
    int col = t - v * FEAT4;

    int cnt = __ldg(&g_counts[v]);
    const int4* inv4 = (const int4*)g_inv;
    int4 a = __ldg(&inv4[v * 2 + 0]);     // slots 0..3
    int4 b = __ldg(&inv4[v * 2 + 1]);     // slots 4..7

    float4 s = make_float4(0.f, 0.f, 0.f, 0.f);

    if (cnt == 6) {
        // Fully unrolled: 6 independent 16B loads in flight.
        float4 f0 = __ldg(&ff[a.x * FEAT4 + col]);
        float4 f1 = __ldg(&ff[a.y * FEAT4 + col]);
        float4 f2 = __ldg(&ff[a.z * FEAT4 + col]);
        float4 f3 = __ldg(&ff[a.w * FEAT4 + col]);
        float4 f4 = __ldg(&ff[b.x * FEAT4 + col]);
        float4 f5 = __ldg(&ff[b.y * FEAT4 + col]);
        s.x = ((f0.x + f1.x) + (f2.x + f3.x)) + (f4.x + f5.x);
        s.y = ((f0.y + f1.y) + (f2.y + f3.y)) + (f4.y + f5.y);
        s.z = ((f0.z + f1.z) + (f2.z + f3.z)) + (f4.z + f5.z);
        s.w = ((f0.w + f1.w) + (f2.w + f3.w)) + (f4.w + f5.w);
    } else {
        int ids[STRIDE] = {a.x, a.y, a.z, a.w, b.x, b.y, b.z, b.w};
        int m = cnt < STRIDE ? cnt : STRIDE;
        for (int j = 0; j < m; ++j) {
            float4 f = __ldg(&ff[ids[j] * FEAT4 + col]);
            s.x += f.x; s.y += f.y; s.z += f.z; s.w += f.w;
        }
    }

    float r = 1.0f / (float)cnt;   // cnt>=1 guaranteed (no orphan vertices)
    s.x *= r; s.y *= r; s.z *= r; s.w *= r;
    out[t] = s;
}

// ---------------------------------------------------------------------------
// Launch: 3 sequential kernels on the default stream (graph-capturable,
// allocation-free; scratch lives in __device__ globals).
// Inputs per metadata order: [0]=face_features (float32 F*576),
// [1]=faces (int32 or int64, 3F elements), [2]=vertex_count (unused; V derived
// from out_size).
// ---------------------------------------------------------------------------
extern "C" void kernel_launch(void* const* d_in, const int* in_sizes, int n_in,
                              void* d_out, int out_size)
{
    const float* ff   = (const float*)d_in[0];
    const void* faces = d_in[1];
    int n_corners = in_sizes[1];
    int V = out_size / FEAT;
    if (V > V_MAX) V = V_MAX;                       // scratch bound (exact for this problem)
    if (n_corners > V_MAX * STRIDE) n_corners = V_MAX * STRIDE;

    zero_detect_kernel<<<(V + 255) / 256, 256>>>((const unsigned int*)faces, V);
    build_inv_kernel<<<(n_corners + 255) / 256, 256>>>(faces, n_corners, V);

    int total = V * FEAT4;
    gather_mean_kernel<<<(total + 255) / 256, 256>>>((const float4*)ff,
                                                     (float4*)d_out, V);
}

// round 2
// speedup vs baseline: 1.0169x; 1.0169x over previous
#include <cuda_runtime.h>
#include <stdint.h>

// Problem constants (from reference): FEAT=192 per corner, V=98304, 3F=589824.
// Every vertex has degree exactly 6, but counts are computed dynamically with
// STRIDE=8 slack for safety.
#define FEAT    192
#define FEAT4   48          // FEAT / 4 (float4 columns)
#define V_MAX   98304
#define STRIDE  8           // padded slots per vertex in the inverse map

__device__ int g_counts[V_MAX];
__device__ int g_inv[V_MAX * STRIDE];

// ---------------------------------------------------------------------------
// Kernel 1: build inverse map vertex -> corner ids via int atomics.
// Dtype detection (int32 vs int64 faces) is folded in per-block: for int64
// little-endian indices < 2^31 every odd 32-bit word is zero; 32 consecutive
// zero odd-words from random int32 vertex ids has probability ~(1/V)^32 ~ 0.
// The 64 words probed are L2-resident after the first block -> ~free.
// ---------------------------------------------------------------------------
__global__ void build_inv_kernel(const void* __restrict__ faces, int n_corners, int V)
{
    __shared__ int s_is64;
    if (threadIdx.x < 32) {
        unsigned int w = __ldg(((const unsigned int*)faces) + 2 * threadIdx.x + 1);
        unsigned int mask = __ballot_sync(0xffffffffu, w == 0u);
        if (threadIdx.x == 0) s_is64 = (mask == 0xffffffffu) ? 1 : 0;
    }
    __syncthreads();
    int is64 = s_is64;

    int c = blockIdx.x * blockDim.x + threadIdx.x;
    if (c >= n_corners) return;
    int v;
    if (is64) {
        v = (int)__ldg(((const long long*)faces) + c);
    } else {
        v = __ldg(((const int*)faces) + c);
    }
    if ((unsigned)v >= (unsigned)V) return;  // defensive; never taken on valid input
    int slot = atomicAdd(&g_counts[v], 1);
    if (slot < STRIDE) g_inv[v * STRIDE + slot] = c;
}

// ---------------------------------------------------------------------------
// Kernel 2: gather + mean. One thread per (vertex, float4-column).
// 48 threads cooperate on one vertex; each reads up to STRIDE corner rows'
// float4 at its column (LDG.128, coalesced 768B row segments), sums, scales
// by 1/count, writes once (STG.128).
//   __ldcs on ff:  each ff row is read exactly once -> evict-first keeps L2
//                  capacity for the hot g_inv/g_counts arrays.
//   __stcs on out: write-once 75MB stream, no reuse -> don't pollute L2.
// Fast path fully unrolled for count==6 (always true here) -> 6 independent
// in-flight LDG.128 per thread.
// ---------------------------------------------------------------------------
__global__ void __launch_bounds__(256)
gather_mean_kernel(const float4* __restrict__ ff, float4* __restrict__ out, int V)
{
    int t = blockIdx.x * blockDim.x + threadIdx.x;
    int total = V * FEAT4;
    if (t >= total) return;
    int v   = t / FEAT4;       // const divisor -> mul/shift
    int col = t - v * FEAT4;

    int cnt = __ldg(&g_counts[v]);
    const int4* inv4 = (const int4*)g_inv;
    int4 a = __ldg(&inv4[v * 2 + 0]);     // slots 0..3
    int4 b = __ldg(&inv4[v * 2 + 1]);     // slots 4..7

    float4 s = make_float4(0.f, 0.f, 0.f, 0.f);

    if (cnt == 6) {
        float4 f0 = __ldcs(&ff[a.x * FEAT4 + col]);
        float4 f1 = __ldcs(&ff[a.y * FEAT4 + col]);
        float4 f2 = __ldcs(&ff[a.z * FEAT4 + col]);
        float4 f3 = __ldcs(&ff[a.w * FEAT4 + col]);
        float4 f4 = __ldcs(&ff[b.x * FEAT4 + col]);
        float4 f5 = __ldcs(&ff[b.y * FEAT4 + col]);
        s.x = ((f0.x + f1.x) + (f2.x + f3.x)) + (f4.x + f5.x);
        s.y = ((f0.y + f1.y) + (f2.y + f3.y)) + (f4.y + f5.y);
        s.z = ((f0.z + f1.z) + (f2.z + f3.z)) + (f4.z + f5.z);
        s.w = ((f0.w + f1.w) + (f2.w + f3.w)) + (f4.w + f5.w);
    } else {
        int ids[STRIDE] = {a.x, a.y, a.z, a.w, b.x, b.y, b.z, b.w};
        int m = cnt < STRIDE ? cnt : STRIDE;
        for (int j = 0; j < m; ++j) {
            float4 f = __ldcs(&ff[ids[j] * FEAT4 + col]);
            s.x += f.x; s.y += f.y; s.z += f.z; s.w += f.w;
        }
    }

    float r = 1.0f / (float)cnt;   // cnt>=1 guaranteed (no orphan vertices)
    s.x *= r; s.y *= r; s.z *= r; s.w *= r;
    __stcs(&out[t], s);
}

// ---------------------------------------------------------------------------
// Launch: memset node + 2 kernels on the default stream (graph-capturable,
// allocation-free; scratch lives in __device__ globals).
// Inputs: [0]=face_features (float32 F*576), [1]=faces (int32 or int64, 3F),
// [2]=vertex_count (unused; V derived from out_size).
// ---------------------------------------------------------------------------
extern "C" void kernel_launch(void* const* d_in, const int* in_sizes, int n_in,
                              void* d_out, int out_size)
{
    const float* ff   = (const float*)d_in[0];
    const void* faces = d_in[1];
    int n_corners = in_sizes[1];
    int V = out_size / FEAT;
    if (V > V_MAX) V = V_MAX;                       // scratch bound (exact here)
    if (n_corners > V_MAX * STRIDE) n_corners = V_MAX * STRIDE;

    void* counts_ptr = nullptr;
    cudaGetSymbolAddress(&counts_ptr, g_counts);    // no alloc; query only
    cudaMemsetAsync(counts_ptr, 0, (size_t)V * sizeof(int));

    build_inv_kernel<<<(n_corners + 255) / 256, 256>>>(faces, n_corners, V);

    int total = V * FEAT4;
    gather_mean_kernel<<<(total + 255) / 256, 256>>>((const float4*)ff,
                                                     (float4*)d_out, V);
}